// round 15
// baseline (speedup 1.0000x reference)
#include <cuda_runtime.h>
#include <cuda_fp16.h>
#include <math.h>
#include <stdint.h>

#define BATCH 8
#define SEQ   2048
#define DIM   1024
#define MTOT  (BATCH * SEQ)   // 16384
#define DD    ((size_t)DIM * DIM)

#define NBF ((size_t)MTOT * DIM)         // 16,777,216
#define NSC ((size_t)BATCH * SEQ * SEQ)  // 33,554,432

// ===================== scratch (no cudaMalloc allowed) =====================
__device__ __align__(1024) __half g_inh[3 * NBF];   // hi: [0]=queries [1]=keys [2]=values
__device__ __align__(1024) __half g_inl[2 * NBF];   // lo: [0]=queries [1]=keys
__device__ __align__(1024) __half g_qkph[2 * NBF];  // [0]=q-proj hi, [1]=k-proj hi
__device__ __align__(1024) __half g_qkpl[2 * NBF];  // [0]=q-proj lo, [1]=k-proj lo
__device__ __align__(1024) __half g_vgh[2 * NBF];   // [0]=v-proj hi, [1]=gpre hi
__device__ __align__(1024) __half g_gch[NBF];       // gated context hi
__device__ __align__(1024) __half g_ah[NSC];        // softmax(attn) hi
__device__ __align__(1024) __half g_W[7 * DD];      // 0=Wqh 1=Wql 2=Wkh 3=Wkl 4=Wvh 5=Wgh 6=Woh
__device__ __align__(1024) float g_scores[NSC];
__device__ __align__(1024) float g_bias[4 * DIM];   // 0=bq 1=bk 2=bv 3=bg

// ===================== PTX wrappers =====================
__device__ __forceinline__ uint32_t smem_u32(const void* p) {
    uint32_t a;
    asm("{ .reg .u64 t; cvta.to.shared.u64 t, %1; cvt.u32.u64 %0, t; }" : "=r"(a) : "l"(p));
    return a;
}
__device__ __forceinline__ void cpa16(uint32_t dst, const void* src) {
    asm volatile("cp.async.cg.shared.global [%0], [%1], 16;" :: "r"(dst), "l"(src));
}
__device__ __forceinline__ void cp_commit() {
    asm volatile("cp.async.commit_group;" ::: "memory");
}
template <int N>
__device__ __forceinline__ void cp_wait() {
    asm volatile("cp.async.wait_group %0;" :: "n"(N) : "memory");
}
__device__ __forceinline__ void ldm4(uint32_t r[4], uint32_t addr) {
    asm volatile("ldmatrix.sync.aligned.m8n8.x4.shared.b16 {%0,%1,%2,%3}, [%4];"
                 : "=r"(r[0]), "=r"(r[1]), "=r"(r[2]), "=r"(r[3]) : "r"(addr));
}
__device__ __forceinline__ void ldm4t(uint32_t r[4], uint32_t addr) {
    asm volatile("ldmatrix.sync.aligned.m8n8.x4.trans.shared.b16 {%0,%1,%2,%3}, [%4];"
                 : "=r"(r[0]), "=r"(r[1]), "=r"(r[2]), "=r"(r[3]) : "r"(addr));
}
__device__ __forceinline__ void mma16816(float c[4],
                                         const uint32_t a[4],
                                         uint32_t b0, uint32_t b1) {
    asm volatile(
        "mma.sync.aligned.m16n8k16.row.col.f32.f16.f16.f32 "
        "{%0,%1,%2,%3}, {%4,%5,%6,%7}, {%8,%9}, {%0,%1,%2,%3};"
        : "+f"(c[0]), "+f"(c[1]), "+f"(c[2]), "+f"(c[3])
        : "r"(a[0]), "r"(a[1]), "r"(a[2]), "r"(a[3]), "r"(b0), "r"(b1));
}
__device__ __forceinline__ void split2h(float x, __half& h, __half& l) {
    h = __float2half_rn(x);
    l = __float2half_rn(x - __half2float(h));
}
__device__ __forceinline__ float sigmoidf_(float x) {
    return 1.0f / (1.0f + __expf(-x));
}

// ===================== fp16 split HMMA GEMM =====================
// CTA tile 128x128, 128 threads / 4 warps, warp tile 64x64.
// NPASS=3: Ah*Bh + Ah*Bl + Al*Bh  (4 smem slots/stage, 2 stages, wait<0>)
// NPASS=1: Ah*Bh                  (2 slots/stage, 4 stages, wait<=2 lookahead)
// TRANSB=false: B stored [n][k]. TRANSB=true: B stored [k][n].
// OMODE 0: fp32 out (+bias). OMODE 1: fp16 hi/lo pair (+bias). OMODE 2: fp16 hi (+bias).
// OMODE 3: gated fp16 hi: val * sigmoid(gpre_h), gpre_h passed via cl.
// blockIdx.z strides all pointers; bias += z*sbias.
#define PA_E   40
#define PA_B   (PA_E * 2)    // 80 bytes
#define PBT_E  136
#define PBT_B  (PBT_E * 2)   // 272 bytes
#define MAT_BYTES   10240

template <int NPASS> struct GemmCfg {
    static constexpr int A_SLOTS = (NPASS == 3) ? 2 : 1;
    static constexpr int B_SLOTS = (NPASS >= 2) ? 2 : 1;
    static constexpr int STAGE   = (A_SLOTS + B_SLOTS) * MAT_BYTES;
    static constexpr int NST     = (NPASS == 1) ? 4 : 2;
    static constexpr int SMEM    = NST * STAGE;
};

template <bool TRANSB, int NPASS, int OMODE>
__global__ void __launch_bounds__(128, 2)
hgemm(const __half* __restrict__ gAh, const __half* __restrict__ gAl,
      const __half* __restrict__ gBh, const __half* __restrict__ gBl,
      float* __restrict__ cf,
      __half* __restrict__ ch, __half* __restrict__ cl,
      const float* __restrict__ bias,
      int lda, int ldb, int ldc, int K,
      long long sa, long long sb, long long sc, int sbias)
{
    using CFG = GemmCfg<NPASS>;
    extern __shared__ __align__(128) char smem[];
    const uint32_t sbase = smem_u32(smem);

    const int tid  = threadIdx.x;
    const int wid  = tid >> 5;
    const int lane = tid & 31;
    const int m0   = blockIdx.y * 128;
    const int n0   = blockIdx.x * 128;
    const int z    = blockIdx.z;

    gAh += (long long)z * sa;
    if (NPASS == 3) gAl += (long long)z * sa;
    gBh += (long long)z * sb;
    if (NPASS >= 2) gBl += (long long)z * sb;
    if (bias) bias += (long long)z * sbias;

    const int wm0 = (wid >> 1) * 64;
    const int wn0 = (wid & 1) * 64;

    float acc[4][8][4];
    #pragma unroll
    for (int i = 0; i < 4; i++)
        #pragma unroll
        for (int j = 0; j < 8; j++)
            #pragma unroll
            for (int r = 0; r < 4; r++) acc[i][j][r] = 0.0f;

    const int nchunks = K >> 5;

    // ------- stage loader (128 threads) -------
    auto load_stage = [&](int s, int k0) {
        const uint32_t st = sbase + s * CFG::STAGE;
        const uint32_t bst = st + CFG::A_SLOTS * MAT_BYTES;
        #pragma unroll
        for (int j = 0; j < 4; j++) {
            const int c = tid + 128 * j;
            {   // A: 128 rows x 32 cols
                const int row = c >> 2, col = c & 3;
                const uint32_t so = st + row * PA_B + col * 16;
                const long long go = (long long)(m0 + row) * lda + k0 + col * 8;
                cpa16(so, gAh + go);
                if (NPASS == 3) cpa16(so + MAT_BYTES, gAl + go);
            }
            if (TRANSB) {   // B: 32 rows (k) x 128 cols (n)
                const int row = c >> 4, col = c & 15;
                const uint32_t so = bst + row * PBT_B + col * 16;
                const long long go = (long long)(k0 + row) * ldb + n0 + col * 8;
                cpa16(so, gBh + go);
                if (NPASS >= 2) cpa16(so + MAT_BYTES, gBl + go);
            } else {        // B: 128 rows (n) x 32 cols (k)
                const int row = c >> 2, col = c & 3;
                const uint32_t so = bst + row * PA_B + col * 16;
                const long long go = (long long)(n0 + row) * ldb + k0 + col * 8;
                cpa16(so, gBh + go);
                if (NPASS >= 2) cpa16(so + MAT_BYTES, gBl + go);
            }
        }
    };

    // ------- compute one stage -------
    auto compute_stage = [&](int s) {
        const uint32_t ab = sbase + s * CFG::STAGE;
        const uint32_t bb = ab + CFG::A_SLOTS * MAT_BYTES;
        #pragma unroll
        for (int ks = 0; ks < 32; ks += 16) {
            uint32_t ah[4][4], al[4][4];
            #pragma unroll
            for (int im = 0; im < 4; im++) {
                const uint32_t addr = ab
                    + (wm0 + im * 16 + (lane & 15)) * PA_B
                    + (ks + ((lane >> 4) << 3)) * 2;
                ldm4(ah[im], addr);
                if (NPASS == 3) ldm4(al[im], addr + MAT_BYTES);
            }
            #pragma unroll
            for (int half = 0; half < 4; half++) {
                const int nb = wn0 + half * 16;
                uint32_t rh[4], rl[4];
                if (TRANSB) {
                    const int krow = ks + (lane & 7) + (((lane >> 3) & 1) << 3);
                    const int ncol = nb + ((lane >> 4) << 3);
                    const uint32_t addr = bb + krow * PBT_B + ncol * 2;
                    ldm4t(rh, addr);
                    if (NPASS >= 2) ldm4t(rl, addr + MAT_BYTES);
                } else {
                    const int nrow = nb + (lane & 7) + ((lane >> 4) << 3);
                    const int kcol = ks + (((lane >> 3) & 1) << 3);
                    const uint32_t addr = bb + nrow * PA_B + kcol * 2;
                    ldm4(rh, addr);
                    if (NPASS >= 2) ldm4(rl, addr + MAT_BYTES);
                }
                #pragma unroll
                for (int im = 0; im < 4; im++) {
                    mma16816(acc[im][2*half],   ah[im], rh[0], rh[1]);
                    if (NPASS >= 2) mma16816(acc[im][2*half], ah[im], rl[0], rl[1]);
                    if (NPASS == 3) mma16816(acc[im][2*half], al[im], rh[0], rh[1]);
                    mma16816(acc[im][2*half+1], ah[im], rh[2], rh[3]);
                    if (NPASS >= 2) mma16816(acc[im][2*half+1], ah[im], rl[2], rl[3]);
                    if (NPASS == 3) mma16816(acc[im][2*half+1], al[im], rh[2], rh[3]);
                }
            }
        }
    };

    // ------- pipeline -------
    // NST=2: wait<0> -> sync -> load(c+1) -> compute(c)
    // NST=4: prologue loads chunks 0..2; at iter c, outstanding = min(3, nchunks-c)
    //        groups -> wait so that chunk c is complete, keeping up to 2 in flight.
    load_stage(0, 0);
    cp_commit();
    if (CFG::NST == 4) {
        if (nchunks > 1) { load_stage(1, 32); cp_commit(); }
        if (nchunks > 2) { load_stage(2, 64); cp_commit(); }
    }
    for (int c = 0; c < nchunks; c++) {
        if (CFG::NST == 4) {
            const int rem = nchunks - c;
            if (rem >= 3)      cp_wait<2>();
            else if (rem == 2) cp_wait<1>();
            else               cp_wait<0>();
        } else {
            cp_wait<0>();
        }
        __syncthreads();
        const int next = c + CFG::NST - 1;
        if (next < nchunks) { load_stage(next % CFG::NST, next * 32); cp_commit(); }
        compute_stage(c % CFG::NST);
    }

    // ------- epilogue -------
    const long long zc = (long long)z * sc;
    #pragma unroll
    for (int im = 0; im < 4; im++) {
        #pragma unroll
        for (int in = 0; in < 8; in++) {
            const int mr = m0 + wm0 + im * 16 + (lane >> 2);
            const int nc = n0 + wn0 + in * 8 + ((lane & 3) << 1);
            float bx = 0.0f, by = 0.0f;
            if (OMODE != 3 && bias) {
                float2 bb = *reinterpret_cast<const float2*>(&bias[nc]);
                bx = bb.x; by = bb.y;
            }
            float v0 = acc[im][in][0] + bx;
            float v1 = acc[im][in][1] + by;
            float v2 = acc[im][in][2] + bx;
            float v3 = acc[im][in][3] + by;
            const long long o0 = zc + (long long)mr * ldc + nc;
            const long long o1 = zc + (long long)(mr + 8) * ldc + nc;
            if (OMODE == 0) {
                *reinterpret_cast<float2*>(&cf[o0]) = make_float2(v0, v1);
                *reinterpret_cast<float2*>(&cf[o1]) = make_float2(v2, v3);
            } else if (OMODE == 2 || OMODE == 3) {
                if (OMODE == 3) {
                    __half2 g01 = *reinterpret_cast<const __half2*>(&cl[o0]);
                    __half2 g23 = *reinterpret_cast<const __half2*>(&cl[o1]);
                    v0 *= sigmoidf_(__half2float(g01.x));
                    v1 *= sigmoidf_(__half2float(g01.y));
                    v2 *= sigmoidf_(__half2float(g23.x));
                    v3 *= sigmoidf_(__half2float(g23.y));
                }
                *reinterpret_cast<__half2*>(&ch[o0]) =
                    __halves2half2(__float2half_rn(v0), __float2half_rn(v1));
                *reinterpret_cast<__half2*>(&ch[o1]) =
                    __halves2half2(__float2half_rn(v2), __float2half_rn(v3));
            } else {
                __half h0, l0, h1, l1, h2, l2, h3, l3;
                split2h(v0, h0, l0); split2h(v1, h1, l1);
                split2h(v2, h2, l2); split2h(v3, h3, l3);
                *reinterpret_cast<__half2*>(&ch[o0]) = __halves2half2(h0, h1);
                *reinterpret_cast<__half2*>(&ch[o1]) = __halves2half2(h2, h3);
                *reinterpret_cast<__half2*>(&cl[o0]) = __halves2half2(l0, l1);
                *reinterpret_cast<__half2*>(&cl[o1]) = __halves2half2(l2, l3);
            }
        }
    }
}

// ===================== glue kernels =====================
// fused input split: z=0 queries(pair), z=1 keys(pair), z=2 values(hi only)
__global__ __launch_bounds__(256)
void split_inputs_kernel(const float* __restrict__ q, const float* __restrict__ k,
                         const float* __restrict__ v,
                         __half* __restrict__ hi, __half* __restrict__ lo)
{
    const int z = blockIdx.y;
    const float* src = (z == 0) ? q : (z == 1) ? k : v;
    const size_t i = ((size_t)blockIdx.x * 256 + threadIdx.x) * 4;
    float4 x = *reinterpret_cast<const float4*>(src + i);
    const size_t o = (size_t)z * NBF + i;
    if (z < 2) {
        __half h0,l0,h1,l1,h2,l2,h3,l3;
        split2h(x.x, h0, l0); split2h(x.y, h1, l1); split2h(x.z, h2, l2); split2h(x.w, h3, l3);
        *reinterpret_cast<__half2*>(hi + o)     = __halves2half2(h0, h1);
        *reinterpret_cast<__half2*>(hi + o + 2) = __halves2half2(h2, h3);
        *reinterpret_cast<__half2*>(lo + o)     = __halves2half2(l0, l1);
        *reinterpret_cast<__half2*>(lo + o + 2) = __halves2half2(l2, l3);
    } else {
        *reinterpret_cast<__half2*>(hi + o)     = __halves2half2(__float2half_rn(x.x), __float2half_rn(x.y));
        *reinterpret_cast<__half2*>(hi + o + 2) = __halves2half2(__float2half_rn(x.z), __float2half_rn(x.w));
    }
}

// fused weight prep: z=0 Wq(pair->0/1), z=1 Wk(pair->2/3), z=2 Wv(hi->4),
// z=3 Wg(hi->5), z=4 Wo(hi->6)
__global__ __launch_bounds__(256)
void prep_weights_kernel(const float* __restrict__ Wq, const float* __restrict__ Wk,
                         const float* __restrict__ Wv, const float* __restrict__ Wg,
                         const float* __restrict__ Wo, __half* __restrict__ Wt)
{
    const int z = blockIdx.y;
    const float* src = (z == 0) ? Wq : (z == 1) ? Wk : (z == 2) ? Wv : (z == 3) ? Wg : Wo;
    const size_t i = ((size_t)blockIdx.x * 256 + threadIdx.x) * 4;
    float4 x = *reinterpret_cast<const float4*>(src + i);
    if (z < 2) {
        __half* hi = Wt + (size_t)(2 * z) * DD;
        __half* lo = Wt + (size_t)(2 * z + 1) * DD;
        __half h0,l0,h1,l1,h2,l2,h3,l3;
        split2h(x.x, h0, l0); split2h(x.y, h1, l1); split2h(x.z, h2, l2); split2h(x.w, h3, l3);
        *reinterpret_cast<__half2*>(hi + i)     = __halves2half2(h0, h1);
        *reinterpret_cast<__half2*>(hi + i + 2) = __halves2half2(h2, h3);
        *reinterpret_cast<__half2*>(lo + i)     = __halves2half2(l0, l1);
        *reinterpret_cast<__half2*>(lo + i + 2) = __halves2half2(l2, l3);
    } else {
        __half* hi = Wt + (size_t)(z + 2) * DD;   // z=2->4, z=3->5, z=4->6
        *reinterpret_cast<__half2*>(hi + i)     = __halves2half2(__float2half_rn(x.x), __float2half_rn(x.y));
        *reinterpret_cast<__half2*>(hi + i + 2) = __halves2half2(__float2half_rn(x.z), __float2half_rn(x.w));
    }
}

__global__ __launch_bounds__(256)
void gather_bias_kernel(const float* __restrict__ b0, const float* __restrict__ b1,
                        const float* __restrict__ b2, const float* __restrict__ b3,
                        float* __restrict__ out)
{
    const int v = blockIdx.x;
    const float* src = (v == 0) ? b0 : (v == 1) ? b1 : (v == 2) ? b2 : b3;
    for (int j = threadIdx.x; j < DIM; j += 256) out[(size_t)v * DIM + j] = src[j];
}

// row softmax (len 2048) -> fp16 hi
__global__ __launch_bounds__(256)
void softmax_h_kernel(const float* __restrict__ S, __half* __restrict__ ah)
{
    const size_t row = blockIdx.x;
    const float4* p4 = reinterpret_cast<const float4*>(S + row * SEQ);
    const int tid = threadIdx.x;
    __shared__ float red[8];

    float4 v[2];
    float mx = -1e30f;
    #pragma unroll
    for (int i = 0; i < 2; i++) {
        v[i] = p4[i * 256 + tid];
        mx = fmaxf(mx, fmaxf(fmaxf(v[i].x, v[i].y), fmaxf(v[i].z, v[i].w)));
    }
    #pragma unroll
    for (int o = 16; o; o >>= 1) mx = fmaxf(mx, __shfl_xor_sync(0xffffffffu, mx, o));
    if ((tid & 31) == 0) red[tid >> 5] = mx;
    __syncthreads();
    mx = red[0];
    #pragma unroll
    for (int i = 1; i < 8; i++) mx = fmaxf(mx, red[i]);
    __syncthreads();

    float s = 0.0f;
    #pragma unroll
    for (int i = 0; i < 2; i++) {
        v[i].x = __expf(v[i].x - mx); v[i].y = __expf(v[i].y - mx);
        v[i].z = __expf(v[i].z - mx); v[i].w = __expf(v[i].w - mx);
        s += v[i].x + v[i].y + v[i].z + v[i].w;
    }
    #pragma unroll
    for (int o = 16; o; o >>= 1) s += __shfl_xor_sync(0xffffffffu, s, o);
    if ((tid & 31) == 0) red[tid >> 5] = s;
    __syncthreads();
    s = red[0];
    #pragma unroll
    for (int i = 1; i < 8; i++) s += red[i];

    const float inv = 1.0f / s;
    #pragma unroll
    for (int i = 0; i < 2; i++) {
        const size_t e = row * SEQ + ((size_t)i * 256 + tid) * 4;
        *reinterpret_cast<__half2*>(ah + e) =
            __halves2half2(__float2half_rn(v[i].x * inv), __float2half_rn(v[i].y * inv));
        *reinterpret_cast<__half2*>(ah + e + 2) =
            __halves2half2(__float2half_rn(v[i].z * inv), __float2half_rn(v[i].w * inv));
    }
}

// ===================== host =====================
extern "C" void kernel_launch(void* const* d_in, const int* in_sizes, int n_in,
                              void* d_out, int out_size)
{
    (void)in_sizes; (void)n_in; (void)out_size;

    const float* queries = (const float*)d_in[0];
    const float* keys    = (const float*)d_in[1];
    const float* values  = (const float*)d_in[2];
    const float* Wq = (const float*)d_in[3];
    const float* bq = (const float*)d_in[4];
    const float* Wk = (const float*)d_in[5];
    const float* bk = (const float*)d_in[6];
    const float* Wv = (const float*)d_in[7];
    const float* bv = (const float*)d_in[8];
    const float* Wg = (const float*)d_in[9];
    const float* bg = (const float*)d_in[10];
    const float* Wo = (const float*)d_in[11];
    const float* bo = (const float*)d_in[12];
    float* out = (float*)d_out;

    void *inh, *inl, *qkph, *qkpl, *vgh, *gch, *ah, *scores, *Wbase, *biasb;
    cudaGetSymbolAddress(&inh, g_inh);   cudaGetSymbolAddress(&inl, g_inl);
    cudaGetSymbolAddress(&qkph, g_qkph); cudaGetSymbolAddress(&qkpl, g_qkpl);
    cudaGetSymbolAddress(&vgh, g_vgh);   cudaGetSymbolAddress(&gch, g_gch);
    cudaGetSymbolAddress(&ah, g_ah);     cudaGetSymbolAddress(&scores, g_scores);
    cudaGetSymbolAddress(&Wbase, g_W);   cudaGetSymbolAddress(&biasb, g_bias);
    __half* INH = (__half*)inh;  __half* INL = (__half*)inl;
    __half* QKH = (__half*)qkph; __half* QKL = (__half*)qkpl;
    __half* VGH = (__half*)vgh;
    __half* Wt  = (__half*)Wbase;
    float*  BIA = (float*)biasb;

    const int SMEM3 = GemmCfg<3>::SMEM;   // 81920
    const int SMEM1 = GemmCfg<1>::SMEM;   // 81920 (4 stages x 20480)

    cudaFuncSetAttribute(hgemm<true,  3, 1>, cudaFuncAttributeMaxDynamicSharedMemorySize, SMEM3);
    cudaFuncSetAttribute(hgemm<false, 3, 0>, cudaFuncAttributeMaxDynamicSharedMemorySize, SMEM3);
    cudaFuncSetAttribute(hgemm<true,  1, 2>, cudaFuncAttributeMaxDynamicSharedMemorySize, SMEM1);
    cudaFuncSetAttribute(hgemm<true,  1, 3>, cudaFuncAttributeMaxDynamicSharedMemorySize, SMEM1);
    cudaFuncSetAttribute(hgemm<true,  1, 0>, cudaFuncAttributeMaxDynamicSharedMemorySize, SMEM1);

    // ---- 1. prep: fused input splits + fused weight prep + bias gather ----
    {
        dim3 gi((unsigned)(NBF / 4 / 256), 3);
        split_inputs_kernel<<<gi, 256>>>(queries, keys, values, INH, INL);
        dim3 gw((unsigned)(DD / 4 / 256), 5);
        prep_weights_kernel<<<gw, 256>>>(Wq, Wk, Wv, Wg, Wo, Wt);
        gather_bias_kernel<<<4, 256>>>(bq, bk, bv, bg, BIA);
    }

    // ---- 2a. fused Q+K projections (3-pass, pair out) ----
    {
        dim3 g(DIM / 128, MTOT / 128, 2);
        hgemm<true, 3, 1><<<g, 128, SMEM3>>>(
            INH, INL,
            Wt + 0 * DD, Wt + 1 * DD,
            nullptr, QKH, QKL, BIA,
            DIM, DIM, DIM, DIM,
            (long long)NBF, (long long)(2 * DD), (long long)NBF, DIM);
    }

    // ---- 2b. fused V+G projections (1-pass, hi out) ----
    {
        dim3 g(DIM / 128, MTOT / 128, 2);
        hgemm<true, 1, 2><<<g, 128, SMEM1>>>(
            INH + 2 * NBF, nullptr,           // z0: values, z1: queries (stride -2*NBF)
            Wt + 4 * DD, nullptr,             // z0: Wvh, z1: Wgh (stride DD)
            nullptr, VGH, nullptr, BIA + 2 * DIM,
            DIM, DIM, DIM, DIM,
            -(long long)(2 * NBF), (long long)DD, (long long)NBF, DIM);
    }

    // ---- 3. scores[b] = q[b] @ k[b]^T (3-pass) ----
    {
        dim3 g(SEQ / 128, SEQ / 128, BATCH);
        hgemm<false, 3, 0><<<g, 128, SMEM3>>>(
            QKH, QKL,
            QKH + NBF, QKL + NBF,
            (float*)scores, nullptr, nullptr, nullptr,
            DIM, DIM, SEQ, DIM,
            (long long)SEQ * DIM, (long long)SEQ * DIM, (long long)SEQ * SEQ, 0);
    }

    // ---- 4. softmax -> fp16 hi ----
    softmax_h_kernel<<<BATCH * SEQ, 256>>>((const float*)scores, (__half*)ah);

    // ---- 5. gated ctx = (attn @ v) * sigmoid(gpre)  (1-pass, fused gate) ----
    {
        dim3 g(DIM / 128, SEQ / 128, BATCH);
        hgemm<true, 1, 3><<<g, 128, SMEM1>>>(
            (const __half*)ah, nullptr,
            VGH, nullptr,
            nullptr, (__half*)gch, VGH + NBF,
            nullptr,
            SEQ, DIM, DIM, SEQ,
            (long long)SEQ * SEQ, (long long)SEQ * DIM, (long long)SEQ * DIM, 0);
    }

    // ---- 6. out = gated @ Wo + bo (1-pass) ----
    {
        dim3 g(DIM / 128, MTOT / 128, 1);
        hgemm<true, 1, 0><<<g, 128, SMEM1>>>(
            (const __half*)gch, nullptr,
            Wt + 6 * DD, nullptr,
            out, nullptr, nullptr, bo,
            DIM, DIM, DIM, DIM, 0, 0, 0, 0);
    }
}

// round 16
// speedup vs baseline: 1.0373x; 1.0373x over previous
#include <cuda_runtime.h>
#include <cuda_fp16.h>
#include <math.h>
#include <stdint.h>

#define BATCH 8
#define SEQ   2048
#define DIM   1024
#define MTOT  (BATCH * SEQ)   // 16384
#define DD    ((size_t)DIM * DIM)

#define NBF ((size_t)MTOT * DIM)         // 16,777,216
#define NSC ((size_t)BATCH * SEQ * SEQ)  // 33,554,432

// ===================== scratch (no cudaMalloc allowed) =====================
__device__ __align__(1024) __half g_inh[3 * NBF];   // hi: [0]=queries [1]=keys [2]=values
__device__ __align__(1024) __half g_inl[2 * NBF];   // lo: [0]=queries [1]=keys
__device__ __align__(1024) __half g_qkph[2 * NBF];  // [0]=q-proj hi, [1]=k-proj hi
__device__ __align__(1024) __half g_qkpl[2 * NBF];  // [0]=q-proj lo, [1]=k-proj lo
__device__ __align__(1024) __half g_vgh[2 * NBF];   // [0]=v-proj hi, [1]=gpre hi
__device__ __align__(1024) __half g_gch[NBF];       // gated context hi
__device__ __align__(1024) __half g_ah[NSC];        // softmax(attn) hi
__device__ __align__(1024) __half g_W[7 * DD];      // 0=Wqh 1=Wql 2=Wkh 3=Wkl 4=Wvh 5=Wgh 6=Woh
__device__ __align__(1024) float g_scores[NSC];
__device__ __align__(1024) float g_bias[4 * DIM];   // 0=bq 1=bk 2=bv 3=bg

// ===================== PTX wrappers =====================
__device__ __forceinline__ uint32_t smem_u32(const void* p) {
    uint32_t a;
    asm("{ .reg .u64 t; cvta.to.shared.u64 t, %1; cvt.u32.u64 %0, t; }" : "=r"(a) : "l"(p));
    return a;
}
__device__ __forceinline__ void cpa16(uint32_t dst, const void* src) {
    asm volatile("cp.async.cg.shared.global [%0], [%1], 16;" :: "r"(dst), "l"(src));
}
__device__ __forceinline__ void cp_commit() {
    asm volatile("cp.async.commit_group;" ::: "memory");
}
template <int N>
__device__ __forceinline__ void cp_wait() {
    asm volatile("cp.async.wait_group %0;" :: "n"(N) : "memory");
}
__device__ __forceinline__ void ldm4(uint32_t r[4], uint32_t addr) {
    asm volatile("ldmatrix.sync.aligned.m8n8.x4.shared.b16 {%0,%1,%2,%3}, [%4];"
                 : "=r"(r[0]), "=r"(r[1]), "=r"(r[2]), "=r"(r[3]) : "r"(addr));
}
__device__ __forceinline__ void ldm4t(uint32_t r[4], uint32_t addr) {
    asm volatile("ldmatrix.sync.aligned.m8n8.x4.trans.shared.b16 {%0,%1,%2,%3}, [%4];"
                 : "=r"(r[0]), "=r"(r[1]), "=r"(r[2]), "=r"(r[3]) : "r"(addr));
}
__device__ __forceinline__ void mma16816(float c[4],
                                         const uint32_t a[4],
                                         uint32_t b0, uint32_t b1) {
    asm volatile(
        "mma.sync.aligned.m16n8k16.row.col.f32.f16.f16.f32 "
        "{%0,%1,%2,%3}, {%4,%5,%6,%7}, {%8,%9}, {%0,%1,%2,%3};"
        : "+f"(c[0]), "+f"(c[1]), "+f"(c[2]), "+f"(c[3])
        : "r"(a[0]), "r"(a[1]), "r"(a[2]), "r"(a[3]), "r"(b0), "r"(b1));
}
__device__ __forceinline__ void split2h(float x, __half& h, __half& l) {
    h = __float2half_rn(x);
    l = __float2half_rn(x - __half2float(h));
}
__device__ __forceinline__ float sigmoidf_(float x) {
    return 1.0f / (1.0f + __expf(-x));
}

// ===================== fp16 split HMMA GEMM =====================
// CTA tile 128x128, 128 threads / 4 warps, warp tile 64x64.
// NPASS=3: Ah*Bh + Ah*Bl + Al*Bh  (4 smem slots/stage, 2 stages, wait<0>)
// NPASS=1: Ah*Bh                  (2 slots/stage, 3 stages, wait<1> lookahead)
// TRANSB=false: B stored [n][k]. TRANSB=true: B stored [k][n].
// OMODE 0: fp32 out (+bias). OMODE 1: fp16 hi/lo pair (+bias). OMODE 2: fp16 hi (+bias).
// OMODE 3: gated fp16 hi: val * sigmoid(gpre_h), gpre_h passed via cl.
// blockIdx.z strides all pointers; bias += z*sbias.
#define PA_E   40
#define PA_B   (PA_E * 2)    // 80 bytes
#define PBT_E  136
#define PBT_B  (PBT_E * 2)   // 272 bytes
#define MAT_BYTES   10240

template <int NPASS> struct GemmCfg {
    static constexpr int A_SLOTS = (NPASS == 3) ? 2 : 1;
    static constexpr int B_SLOTS = (NPASS >= 2) ? 2 : 1;
    static constexpr int STAGE   = (A_SLOTS + B_SLOTS) * MAT_BYTES;
    static constexpr int NST     = (NPASS == 1) ? 3 : 2;
    static constexpr int SMEM    = NST * STAGE;
};

template <bool TRANSB, int NPASS, int OMODE>
__global__ void __launch_bounds__(128, 2)
hgemm(const __half* __restrict__ gAh, const __half* __restrict__ gAl,
      const __half* __restrict__ gBh, const __half* __restrict__ gBl,
      float* __restrict__ cf,
      __half* __restrict__ ch, __half* __restrict__ cl,
      const float* __restrict__ bias,
      int lda, int ldb, int ldc, int K,
      long long sa, long long sb, long long sc, int sbias)
{
    using CFG = GemmCfg<NPASS>;
    extern __shared__ __align__(128) char smem[];
    const uint32_t sbase = smem_u32(smem);

    const int tid  = threadIdx.x;
    const int wid  = tid >> 5;
    const int lane = tid & 31;
    const int m0   = blockIdx.y * 128;
    const int n0   = blockIdx.x * 128;
    const int z    = blockIdx.z;

    gAh += (long long)z * sa;
    if (NPASS == 3) gAl += (long long)z * sa;
    gBh += (long long)z * sb;
    if (NPASS >= 2) gBl += (long long)z * sb;
    if (bias) bias += (long long)z * sbias;

    const int wm0 = (wid >> 1) * 64;
    const int wn0 = (wid & 1) * 64;

    float acc[4][8][4];
    #pragma unroll
    for (int i = 0; i < 4; i++)
        #pragma unroll
        for (int j = 0; j < 8; j++)
            #pragma unroll
            for (int r = 0; r < 4; r++) acc[i][j][r] = 0.0f;

    const int nchunks = K >> 5;

    // ------- stage loader (128 threads) -------
    auto load_stage = [&](int s, int k0) {
        const uint32_t st = sbase + s * CFG::STAGE;
        const uint32_t bst = st + CFG::A_SLOTS * MAT_BYTES;
        #pragma unroll
        for (int j = 0; j < 4; j++) {
            const int c = tid + 128 * j;
            {   // A: 128 rows x 32 cols
                const int row = c >> 2, col = c & 3;
                const uint32_t so = st + row * PA_B + col * 16;
                const long long go = (long long)(m0 + row) * lda + k0 + col * 8;
                cpa16(so, gAh + go);
                if (NPASS == 3) cpa16(so + MAT_BYTES, gAl + go);
            }
            if (TRANSB) {   // B: 32 rows (k) x 128 cols (n)
                const int row = c >> 4, col = c & 15;
                const uint32_t so = bst + row * PBT_B + col * 16;
                const long long go = (long long)(k0 + row) * ldb + n0 + col * 8;
                cpa16(so, gBh + go);
                if (NPASS >= 2) cpa16(so + MAT_BYTES, gBl + go);
            } else {        // B: 128 rows (n) x 32 cols (k)
                const int row = c >> 2, col = c & 3;
                const uint32_t so = bst + row * PA_B + col * 16;
                const long long go = (long long)(n0 + row) * ldb + k0 + col * 8;
                cpa16(so, gBh + go);
                if (NPASS >= 2) cpa16(so + MAT_BYTES, gBl + go);
            }
        }
    };

    // ------- compute one stage -------
    auto compute_stage = [&](int s) {
        const uint32_t ab = sbase + s * CFG::STAGE;
        const uint32_t bb = ab + CFG::A_SLOTS * MAT_BYTES;
        #pragma unroll
        for (int ks = 0; ks < 32; ks += 16) {
            uint32_t ah[4][4], al[4][4];
            #pragma unroll
            for (int im = 0; im < 4; im++) {
                const uint32_t addr = ab
                    + (wm0 + im * 16 + (lane & 15)) * PA_B
                    + (ks + ((lane >> 4) << 3)) * 2;
                ldm4(ah[im], addr);
                if (NPASS == 3) ldm4(al[im], addr + MAT_BYTES);
            }
            #pragma unroll
            for (int half = 0; half < 4; half++) {
                const int nb = wn0 + half * 16;
                uint32_t rh[4], rl[4];
                if (TRANSB) {
                    const int krow = ks + (lane & 7) + (((lane >> 3) & 1) << 3);
                    const int ncol = nb + ((lane >> 4) << 3);
                    const uint32_t addr = bb + krow * PBT_B + ncol * 2;
                    ldm4t(rh, addr);
                    if (NPASS >= 2) ldm4t(rl, addr + MAT_BYTES);
                } else {
                    const int nrow = nb + (lane & 7) + ((lane >> 4) << 3);
                    const int kcol = ks + (((lane >> 3) & 1) << 3);
                    const uint32_t addr = bb + nrow * PA_B + kcol * 2;
                    ldm4(rh, addr);
                    if (NPASS >= 2) ldm4(rl, addr + MAT_BYTES);
                }
                #pragma unroll
                for (int im = 0; im < 4; im++) {
                    mma16816(acc[im][2*half],   ah[im], rh[0], rh[1]);
                    if (NPASS >= 2) mma16816(acc[im][2*half], ah[im], rl[0], rl[1]);
                    if (NPASS == 3) mma16816(acc[im][2*half], al[im], rh[0], rh[1]);
                    mma16816(acc[im][2*half+1], ah[im], rh[2], rh[3]);
                    if (NPASS >= 2) mma16816(acc[im][2*half+1], ah[im], rl[2], rl[3]);
                    if (NPASS == 3) mma16816(acc[im][2*half+1], al[im], rh[2], rh[3]);
                }
            }
        }
    };

    // ------- pipeline (R14-proven) -------
    // NST=2: wait<0> -> sync -> load(c+1) -> compute(c)
    // NST=3: prologue loads c=0,1; wait<1> keeps one chunk of lookahead in flight.
    load_stage(0, 0);
    cp_commit();
    if (CFG::NST == 3 && nchunks > 1) { load_stage(1, 32); cp_commit(); }
    for (int c = 0; c < nchunks; c++) {
        const int next = c + CFG::NST - 1;
        if (CFG::NST == 3) {
            if (next < nchunks) cp_wait<1>(); else cp_wait<0>();
        } else {
            cp_wait<0>();
        }
        __syncthreads();
        if (next < nchunks) { load_stage(next % CFG::NST, next * 32); cp_commit(); }
        compute_stage(c % CFG::NST);
    }

    // ------- epilogue -------
    const long long zc = (long long)z * sc;
    #pragma unroll
    for (int im = 0; im < 4; im++) {
        #pragma unroll
        for (int in = 0; in < 8; in++) {
            const int mr = m0 + wm0 + im * 16 + (lane >> 2);
            const int nc = n0 + wn0 + in * 8 + ((lane & 3) << 1);
            float bx = 0.0f, by = 0.0f;
            if (OMODE != 3 && bias) {
                float2 bb = *reinterpret_cast<const float2*>(&bias[nc]);
                bx = bb.x; by = bb.y;
            }
            float v0 = acc[im][in][0] + bx;
            float v1 = acc[im][in][1] + by;
            float v2 = acc[im][in][2] + bx;
            float v3 = acc[im][in][3] + by;
            const long long o0 = zc + (long long)mr * ldc + nc;
            const long long o1 = zc + (long long)(mr + 8) * ldc + nc;
            if (OMODE == 0) {
                *reinterpret_cast<float2*>(&cf[o0]) = make_float2(v0, v1);
                *reinterpret_cast<float2*>(&cf[o1]) = make_float2(v2, v3);
            } else if (OMODE == 2 || OMODE == 3) {
                if (OMODE == 3) {
                    __half2 g01 = *reinterpret_cast<const __half2*>(&cl[o0]);
                    __half2 g23 = *reinterpret_cast<const __half2*>(&cl[o1]);
                    v0 *= sigmoidf_(__half2float(g01.x));
                    v1 *= sigmoidf_(__half2float(g01.y));
                    v2 *= sigmoidf_(__half2float(g23.x));
                    v3 *= sigmoidf_(__half2float(g23.y));
                }
                *reinterpret_cast<__half2*>(&ch[o0]) =
                    __halves2half2(__float2half_rn(v0), __float2half_rn(v1));
                *reinterpret_cast<__half2*>(&ch[o1]) =
                    __halves2half2(__float2half_rn(v2), __float2half_rn(v3));
            } else {
                __half h0, l0, h1, l1, h2, l2, h3, l3;
                split2h(v0, h0, l0); split2h(v1, h1, l1);
                split2h(v2, h2, l2); split2h(v3, h3, l3);
                *reinterpret_cast<__half2*>(&ch[o0]) = __halves2half2(h0, h1);
                *reinterpret_cast<__half2*>(&ch[o1]) = __halves2half2(h2, h3);
                *reinterpret_cast<__half2*>(&cl[o0]) = __halves2half2(l0, l1);
                *reinterpret_cast<__half2*>(&cl[o1]) = __halves2half2(l2, l3);
            }
        }
    }
}

// ===================== glue kernels =====================
// fused input split: z=0 queries(pair), z=1 keys(pair), z=2 values(hi only)
__global__ __launch_bounds__(256)
void split_inputs_kernel(const float* __restrict__ q, const float* __restrict__ k,
                         const float* __restrict__ v,
                         __half* __restrict__ hi, __half* __restrict__ lo)
{
    const int z = blockIdx.y;
    const float* src = (z == 0) ? q : (z == 1) ? k : v;
    const size_t i = ((size_t)blockIdx.x * 256 + threadIdx.x) * 4;
    float4 x = *reinterpret_cast<const float4*>(src + i);
    const size_t o = (size_t)z * NBF + i;
    if (z < 2) {
        __half h0,l0,h1,l1,h2,l2,h3,l3;
        split2h(x.x, h0, l0); split2h(x.y, h1, l1); split2h(x.z, h2, l2); split2h(x.w, h3, l3);
        *reinterpret_cast<__half2*>(hi + o)     = __halves2half2(h0, h1);
        *reinterpret_cast<__half2*>(hi + o + 2) = __halves2half2(h2, h3);
        *reinterpret_cast<__half2*>(lo + o)     = __halves2half2(l0, l1);
        *reinterpret_cast<__half2*>(lo + o + 2) = __halves2half2(l2, l3);
    } else {
        *reinterpret_cast<__half2*>(hi + o)     = __halves2half2(__float2half_rn(x.x), __float2half_rn(x.y));
        *reinterpret_cast<__half2*>(hi + o + 2) = __halves2half2(__float2half_rn(x.z), __float2half_rn(x.w));
    }
}

// fused weight prep: z=0 Wq(pair->0/1), z=1 Wk(pair->2/3), z=2 Wv(hi->4),
// z=3 Wg(hi->5), z=4 Wo(hi->6)
__global__ __launch_bounds__(256)
void prep_weights_kernel(const float* __restrict__ Wq, const float* __restrict__ Wk,
                         const float* __restrict__ Wv, const float* __restrict__ Wg,
                         const float* __restrict__ Wo, __half* __restrict__ Wt)
{
    const int z = blockIdx.y;
    const float* src = (z == 0) ? Wq : (z == 1) ? Wk : (z == 2) ? Wv : (z == 3) ? Wg : Wo;
    const size_t i = ((size_t)blockIdx.x * 256 + threadIdx.x) * 4;
    float4 x = *reinterpret_cast<const float4*>(src + i);
    if (z < 2) {
        __half* hi = Wt + (size_t)(2 * z) * DD;
        __half* lo = Wt + (size_t)(2 * z + 1) * DD;
        __half h0,l0,h1,l1,h2,l2,h3,l3;
        split2h(x.x, h0, l0); split2h(x.y, h1, l1); split2h(x.z, h2, l2); split2h(x.w, h3, l3);
        *reinterpret_cast<__half2*>(hi + i)     = __halves2half2(h0, h1);
        *reinterpret_cast<__half2*>(hi + i + 2) = __halves2half2(h2, h3);
        *reinterpret_cast<__half2*>(lo + i)     = __halves2half2(l0, l1);
        *reinterpret_cast<__half2*>(lo + i + 2) = __halves2half2(l2, l3);
    } else {
        __half* hi = Wt + (size_t)(z + 2) * DD;   // z=2->4, z=3->5, z=4->6
        *reinterpret_cast<__half2*>(hi + i)     = __halves2half2(__float2half_rn(x.x), __float2half_rn(x.y));
        *reinterpret_cast<__half2*>(hi + i + 2) = __halves2half2(__float2half_rn(x.z), __float2half_rn(x.w));
    }
}

__global__ __launch_bounds__(256)
void gather_bias_kernel(const float* __restrict__ b0, const float* __restrict__ b1,
                        const float* __restrict__ b2, const float* __restrict__ b3,
                        float* __restrict__ out)
{
    const int v = blockIdx.x;
    const float* src = (v == 0) ? b0 : (v == 1) ? b1 : (v == 2) ? b2 : b3;
    for (int j = threadIdx.x; j < DIM; j += 256) out[(size_t)v * DIM + j] = src[j];
}

// row softmax (len 2048) -> fp16 hi
__global__ __launch_bounds__(256)
void softmax_h_kernel(const float* __restrict__ S, __half* __restrict__ ah)
{
    const size_t row = blockIdx.x;
    const float4* p4 = reinterpret_cast<const float4*>(S + row * SEQ);
    const int tid = threadIdx.x;
    __shared__ float red[8];

    float4 v[2];
    float mx = -1e30f;
    #pragma unroll
    for (int i = 0; i < 2; i++) {
        v[i] = p4[i * 256 + tid];
        mx = fmaxf(mx, fmaxf(fmaxf(v[i].x, v[i].y), fmaxf(v[i].z, v[i].w)));
    }
    #pragma unroll
    for (int o = 16; o; o >>= 1) mx = fmaxf(mx, __shfl_xor_sync(0xffffffffu, mx, o));
    if ((tid & 31) == 0) red[tid >> 5] = mx;
    __syncthreads();
    mx = red[0];
    #pragma unroll
    for (int i = 1; i < 8; i++) mx = fmaxf(mx, red[i]);
    __syncthreads();

    float s = 0.0f;
    #pragma unroll
    for (int i = 0; i < 2; i++) {
        v[i].x = __expf(v[i].x - mx); v[i].y = __expf(v[i].y - mx);
        v[i].z = __expf(v[i].z - mx); v[i].w = __expf(v[i].w - mx);
        s += v[i].x + v[i].y + v[i].z + v[i].w;
    }
    #pragma unroll
    for (int o = 16; o; o >>= 1) s += __shfl_xor_sync(0xffffffffu, s, o);
    if ((tid & 31) == 0) red[tid >> 5] = s;
    __syncthreads();
    s = red[0];
    #pragma unroll
    for (int i = 1; i < 8; i++) s += red[i];

    const float inv = 1.0f / s;
    #pragma unroll
    for (int i = 0; i < 2; i++) {
        const size_t e = row * SEQ + ((size_t)i * 256 + tid) * 4;
        *reinterpret_cast<__half2*>(ah + e) =
            __halves2half2(__float2half_rn(v[i].x * inv), __float2half_rn(v[i].y * inv));
        *reinterpret_cast<__half2*>(ah + e + 2) =
            __halves2half2(__float2half_rn(v[i].z * inv), __float2half_rn(v[i].w * inv));
    }
}

// ===================== host =====================
extern "C" void kernel_launch(void* const* d_in, const int* in_sizes, int n_in,
                              void* d_out, int out_size)
{
    (void)in_sizes; (void)n_in; (void)out_size;

    const float* queries = (const float*)d_in[0];
    const float* keys    = (const float*)d_in[1];
    const float* values  = (const float*)d_in[2];
    const float* Wq = (const float*)d_in[3];
    const float* bq = (const float*)d_in[4];
    const float* Wk = (const float*)d_in[5];
    const float* bk = (const float*)d_in[6];
    const float* Wv = (const float*)d_in[7];
    const float* bv = (const float*)d_in[8];
    const float* Wg = (const float*)d_in[9];
    const float* bg = (const float*)d_in[10];
    const float* Wo = (const float*)d_in[11];
    const float* bo = (const float*)d_in[12];
    float* out = (float*)d_out;

    void *inh, *inl, *qkph, *qkpl, *vgh, *gch, *ah, *scores, *Wbase, *biasb;
    cudaGetSymbolAddress(&inh, g_inh);   cudaGetSymbolAddress(&inl, g_inl);
    cudaGetSymbolAddress(&qkph, g_qkph); cudaGetSymbolAddress(&qkpl, g_qkpl);
    cudaGetSymbolAddress(&vgh, g_vgh);   cudaGetSymbolAddress(&gch, g_gch);
    cudaGetSymbolAddress(&ah, g_ah);     cudaGetSymbolAddress(&scores, g_scores);
    cudaGetSymbolAddress(&Wbase, g_W);   cudaGetSymbolAddress(&biasb, g_bias);
    __half* INH = (__half*)inh;  __half* INL = (__half*)inl;
    __half* QKH = (__half*)qkph; __half* QKL = (__half*)qkpl;
    __half* VGH = (__half*)vgh;
    __half* Wt  = (__half*)Wbase;
    float*  BIA = (float*)biasb;

    const int SMEM3 = GemmCfg<3>::SMEM;   // 81920
    const int SMEM1 = GemmCfg<1>::SMEM;   // 61440 (3 stages x 20480)

    cudaFuncSetAttribute(hgemm<true,  3, 1>, cudaFuncAttributeMaxDynamicSharedMemorySize, SMEM3);
    cudaFuncSetAttribute(hgemm<false, 3, 0>, cudaFuncAttributeMaxDynamicSharedMemorySize, SMEM3);
    cudaFuncSetAttribute(hgemm<true,  1, 2>, cudaFuncAttributeMaxDynamicSharedMemorySize, SMEM1);
    cudaFuncSetAttribute(hgemm<true,  1, 3>, cudaFuncAttributeMaxDynamicSharedMemorySize, SMEM1);
    cudaFuncSetAttribute(hgemm<true,  1, 0>, cudaFuncAttributeMaxDynamicSharedMemorySize, SMEM1);

    // ---- 1. prep: fused input splits + fused weight prep + bias gather ----
    {
        dim3 gi((unsigned)(NBF / 4 / 256), 3);
        split_inputs_kernel<<<gi, 256>>>(queries, keys, values, INH, INL);
        dim3 gw((unsigned)(DD / 4 / 256), 5);
        prep_weights_kernel<<<gw, 256>>>(Wq, Wk, Wv, Wg, Wo, Wt);
        gather_bias_kernel<<<4, 256>>>(bq, bk, bv, bg, BIA);
    }

    // ---- 2a. fused Q+K projections (3-pass, pair out) ----
    {
        dim3 g(DIM / 128, MTOT / 128, 2);
        hgemm<true, 3, 1><<<g, 128, SMEM3>>>(
            INH, INL,
            Wt + 0 * DD, Wt + 1 * DD,
            nullptr, QKH, QKL, BIA,
            DIM, DIM, DIM, DIM,
            (long long)NBF, (long long)(2 * DD), (long long)NBF, DIM);
    }

    // ---- 2b. fused V+G projections (1-pass, hi out) ----
    {
        dim3 g(DIM / 128, MTOT / 128, 2);
        hgemm<true, 1, 2><<<g, 128, SMEM1>>>(
            INH + 2 * NBF, nullptr,           // z0: values, z1: queries (stride -2*NBF)
            Wt + 4 * DD, nullptr,             // z0: Wvh, z1: Wgh (stride DD)
            nullptr, VGH, nullptr, BIA + 2 * DIM,
            DIM, DIM, DIM, DIM,
            -(long long)(2 * NBF), (long long)DD, (long long)NBF, DIM);
    }

    // ---- 3. scores[b] = q[b] @ k[b]^T (3-pass) ----
    {
        dim3 g(SEQ / 128, SEQ / 128, BATCH);
        hgemm<false, 3, 0><<<g, 128, SMEM3>>>(
            QKH, QKL,
            QKH + NBF, QKL + NBF,
            (float*)scores, nullptr, nullptr, nullptr,
            DIM, DIM, SEQ, DIM,
            (long long)SEQ * DIM, (long long)SEQ * DIM, (long long)SEQ * SEQ, 0);
    }

    // ---- 4. softmax -> fp16 hi ----
    softmax_h_kernel<<<BATCH * SEQ, 256>>>((const float*)scores, (__half*)ah);

    // ---- 5. gated ctx = (attn @ v) * sigmoid(gpre)  (1-pass, fused gate) ----
    {
        dim3 g(DIM / 128, SEQ / 128, BATCH);
        hgemm<true, 1, 3><<<g, 128, SMEM1>>>(
            (const __half*)ah, nullptr,
            VGH, nullptr,
            nullptr, (__half*)gch, VGH + NBF,
            nullptr,
            SEQ, DIM, DIM, SEQ,
            (long long)SEQ * SEQ, (long long)SEQ * DIM, (long long)SEQ * DIM, 0);
    }

    // ---- 6. out = gated @ Wo + bo (1-pass) ----
    {
        dim3 g(DIM / 128, MTOT / 128, 1);
        hgemm<true, 1, 0><<<g, 128, SMEM1>>>(
            (const __half*)gch, nullptr,
            Wt + 6 * DD, nullptr,
            out, nullptr, nullptr, bo,
            DIM, DIM, DIM, DIM, 0, 0, 0, 0);
    }
}